// round 13
// baseline (speedup 1.0000x reference)
#include <cuda_runtime.h>
#include <cuda_bf16.h>
#include <cstdint>

#define T_TOK 16384
#define HDIM  2048
#define QMAX  16256.0f

// ---------------- static device scratch ----------------
__device__ __align__(256) int8_t g_xqh[(size_t)T_TOK * HDIM];
__device__ __align__(256) int8_t g_xql[(size_t)T_TOK * HDIM];
__device__ __align__(256) int8_t g_cqh[(size_t)T_TOK * HDIM];
__device__ __align__(256) int8_t g_cql[(size_t)T_TOK * HDIM];
__device__ float g_sx[T_TOK];
__device__ float g_sc[T_TOK];
__device__ float g_combined[(size_t)T_TOK * HDIM];
__device__ float g_hmid[(size_t)T_TOK * 512];
__device__ float g_mid[(size_t)T_TOK * 1024];           // f32 intermediate (reused)
__device__ __align__(256) int8_t g_q1h[(size_t)T_TOK * 1024];
__device__ __align__(256) int8_t g_q1l[(size_t)T_TOK * 1024];
__device__ __align__(256) int8_t g_q2h[(size_t)T_TOK * 1024];
__device__ __align__(256) int8_t g_q2l[(size_t)T_TOK * 1024];
__device__ float g_s1[T_TOK];
__device__ float g_s2[T_TOK];
__device__ unsigned g_rmax[4 * T_TOK];                  // row-max bits, 4 slots
// transposed+quantized weights pool [N][K] layout (element offsets)
#define O_SELW1 0u
#define O_C1 1048576u
#define O_F1 3145728u
#define O_D1 4194304u
#define O_C2 6291456u
#define O_F2 7340032u
#define O_D2 7602176u
#define W_POOL 8650752u
__device__ __align__(256) int8_t g_wqh[W_POOL];
__device__ __align__(256) int8_t g_wql[W_POOL];
__device__ unsigned g_wmax[7 * 2048];
__device__ int g_sel[T_TOK];
__device__ int g_idx1[T_TOK];
__device__ int g_idx2[T_TOK];
__device__ int g_fix[T_TOK];
__device__ int g_cnt[4];   // [0]=cnt1 [1]=cnt2 [2]=nfix

// ---------------- helpers ----------------
__device__ __forceinline__ uint32_t smem_u32(const void* p) {
    uint32_t a;
    asm("{ .reg .u64 t; cvta.to.shared.u64 t, %1; cvt.u32.u64 %0, t; }" : "=r"(a) : "l"(p));
    return a;
}
__device__ __forceinline__ void cp16(uint32_t dst, const void* src) {
    asm volatile("cp.async.cg.shared.global [%0], [%1], 16;" :: "r"(dst), "l"(src));
}
#define CP_COMMIT() asm volatile("cp.async.commit_group;" ::: "memory")
#define CP_WAIT2()  asm volatile("cp.async.wait_group 2;" ::: "memory")
#define CP_WAIT1()  asm volatile("cp.async.wait_group 1;" ::: "memory")
#define CP_WAIT0()  asm volatile("cp.async.wait_group 0;" ::: "memory")

__device__ __forceinline__ void ldmx4(uint32_t* r, uint32_t addr) {
    asm volatile("ldmatrix.sync.aligned.m8n8.x4.shared.b16 {%0,%1,%2,%3}, [%4];"
        : "=r"(r[0]), "=r"(r[1]), "=r"(r[2]), "=r"(r[3]) : "r"(addr));
}
__device__ __forceinline__ void mma_s8(int* c, const uint32_t* a, uint32_t b0, uint32_t b1) {
    asm volatile("mma.sync.aligned.m16n8k32.row.col.s32.s8.s8.s32 "
        "{%0,%1,%2,%3}, {%4,%5,%6,%7}, {%8,%9}, {%0,%1,%2,%3};"
        : "+r"(c[0]), "+r"(c[1]), "+r"(c[2]), "+r"(c[3])
        : "r"(a[0]), "r"(a[1]), "r"(a[2]), "r"(a[3]), "r"(b0), "r"(b1));
}
__device__ __forceinline__ void qsplit(float v, float inv, int8_t& h, int8_t& l) {
    int q = __float2int_rn(v * inv);
    int hi = (q + 64) >> 7;
    h = (int8_t)hi;
    l = (int8_t)(q - (hi << 7));
}

// ---------------- prep: quantize x & combined (per-token scales), init state ----------------
__global__ void prep_kernel(const float* __restrict__ x, const float* __restrict__ freq,
                            const float* __restrict__ imp) {
    int t = blockIdx.x, tid = threadIdx.x;
    if (t == 0 && tid < 4) g_cnt[tid] = 0;
    if (t < 56)  g_wmax[t * 256 + tid] = 0;
    if (t < 256) g_rmax[t * 256 + tid] = 0;
    const float* xr = x + (size_t)t * HDIM;
    float fq = freq[t], im = imp[t];
    float4 v0 = *(const float4*)(xr + tid * 4);
    float4 v1 = *(const float4*)(xr + 1024 + tid * 4);
    float4 c0, c1v;
    c0.x = v0.x * fq; c0.y = v0.y * fq; c0.z = v0.z * fq; c0.w = v0.w * fq;
    c1v.x = v1.x * im; c1v.y = v1.y * im; c1v.z = v1.z * im; c1v.w = v1.w * im;
    float mx = fmaxf(fmaxf(fabsf(v0.x), fabsf(v0.y)), fmaxf(fabsf(v0.z), fabsf(v0.w)));
    mx = fmaxf(mx, fmaxf(fmaxf(fabsf(v1.x), fabsf(v1.y)), fmaxf(fabsf(v1.z), fabsf(v1.w))));
    float mc = fmaxf(fmaxf(fabsf(c0.x), fabsf(c0.y)), fmaxf(fabsf(c0.z), fabsf(c0.w)));
    mc = fmaxf(mc, fmaxf(fmaxf(fabsf(c1v.x), fabsf(c1v.y)), fmaxf(fabsf(c1v.z), fabsf(c1v.w))));
    __shared__ float sx[256], sc[256];
    sx[tid] = mx; sc[tid] = mc;
    __syncthreads();
    for (int o = 128; o > 0; o >>= 1) {
        if (tid < o) { sx[tid] = fmaxf(sx[tid], sx[tid + o]); sc[tid] = fmaxf(sc[tid], sc[tid + o]); }
        __syncthreads();
    }
    float Sx = sx[0], Sc = sc[0];
    if (tid == 0) { g_sx[t] = Sx; g_sc[t] = Sc; }
    float ivx = Sx > 0.f ? QMAX / Sx : 0.f;
    float ivc = Sc > 0.f ? QMAX / Sc : 0.f;
    size_t e0 = (size_t)t * HDIM + tid * 4, e1 = e0 + 1024;
    *(float4*)(g_combined + e0) = c0;
    *(float4*)(g_combined + e1) = c1v;
    char4 xh0, xl0, xh1, xl1, ch0, cl0, ch1, cl1;
    qsplit(v0.x, ivx, (int8_t&)xh0.x, (int8_t&)xl0.x); qsplit(v0.y, ivx, (int8_t&)xh0.y, (int8_t&)xl0.y);
    qsplit(v0.z, ivx, (int8_t&)xh0.z, (int8_t&)xl0.z); qsplit(v0.w, ivx, (int8_t&)xh0.w, (int8_t&)xl0.w);
    qsplit(v1.x, ivx, (int8_t&)xh1.x, (int8_t&)xl1.x); qsplit(v1.y, ivx, (int8_t&)xh1.y, (int8_t&)xl1.y);
    qsplit(v1.z, ivx, (int8_t&)xh1.z, (int8_t&)xl1.z); qsplit(v1.w, ivx, (int8_t&)xh1.w, (int8_t&)xl1.w);
    qsplit(c0.x, ivc, (int8_t&)ch0.x, (int8_t&)cl0.x); qsplit(c0.y, ivc, (int8_t&)ch0.y, (int8_t&)cl0.y);
    qsplit(c0.z, ivc, (int8_t&)ch0.z, (int8_t&)cl0.z); qsplit(c0.w, ivc, (int8_t&)ch0.w, (int8_t&)cl0.w);
    qsplit(c1v.x, ivc, (int8_t&)ch1.x, (int8_t&)cl1.x); qsplit(c1v.y, ivc, (int8_t&)ch1.y, (int8_t&)cl1.y);
    qsplit(c1v.z, ivc, (int8_t&)ch1.z, (int8_t&)cl1.z); qsplit(c1v.w, ivc, (int8_t&)ch1.w, (int8_t&)cl1.w);
    *(char4*)(g_xqh + e0) = xh0; *(char4*)(g_xql + e0) = xl0;
    *(char4*)(g_xqh + e1) = xh1; *(char4*)(g_xql + e1) = xl1;
    *(char4*)(g_cqh + e0) = ch0; *(char4*)(g_cql + e0) = cl0;
    *(char4*)(g_cqh + e1) = ch1; *(char4*)(g_cql + e1) = cl1;
}

// ---------------- weight prep ----------------
struct WDesc { const float* src; int K; int N; unsigned off; int start; };
struct WAll  { WDesc d[7]; };

// pass 1: per-output-column |max| (32-row slabs, coalesced)
__global__ void wcolmax_kernel(WAll wa) {
    int bt = blockIdx.x;
    int mi = 0;
#pragma unroll
    for (int i = 1; i < 7; i++) if (bt >= wa.d[i].start) mi = i;
    const WDesc& d = wa.d[mi];
    int kb = (bt - d.start) * 32;
    for (int col = threadIdx.x; col < d.N; col += 256) {
        float m = 0.f;
        for (int kk = 0; kk < 32; kk++)
            m = fmaxf(m, fabsf(d.src[(size_t)(kb + kk) * d.N + col]));
        atomicMax(&g_wmax[mi * 2048 + col], __float_as_uint(m));
    }
}

// pass 2: transpose + quantize to int8 limbs [N][K]
__global__ void transpose_quant_kernel(WAll wa) {
    __shared__ float tile[32][33];
    int bt = blockIdx.x;
    int mi = 0;
#pragma unroll
    for (int i = 1; i < 7; i++) if (bt >= wa.d[i].start) mi = i;
    const WDesc& d = wa.d[mi];
    int lt = bt - d.start;
    int ntiles_n = d.N / 32;
    int nb = (lt % ntiles_n) * 32;
    int kb = (lt / ntiles_n) * 32;
#pragma unroll
    for (int r = 0; r < 4; r++) {
        int k = kb + threadIdx.y + r * 8;
        tile[threadIdx.y + r * 8][threadIdx.x] = d.src[(size_t)k * d.N + nb + threadIdx.x];
    }
    __syncthreads();
#pragma unroll
    for (int r = 0; r < 4; r++) {
        int n = nb + threadIdx.y + r * 8;
        int k = kb + threadIdx.x;
        float v = tile[threadIdx.x][threadIdx.y + r * 8];
        float s = __uint_as_float(g_wmax[mi * 2048 + n]);
        float inv = s > 0.f ? QMAX / s : 0.f;
        int8_t h, l; qsplit(v, inv, h, l);
        g_wqh[d.off + (size_t)n * d.K + k] = h;
        g_wql[d.off + (size_t)n * d.K + k] = l;
    }
}

// ---------------- int8 two-limb GEMM ----------------
// CTA tile 128x128, 8 warps each 64x32. K-chunk = 128 int8 (128B rows, SW128).
// 3-stage cp.async ring. acc = 16384*hh + 128*(hi*lo + lo*hi), dequant in epilogue.
#define STAGE_BYTES 65536
#define OFF_AH 0
#define OFF_AL 16384
#define OFF_BH 32768
#define OFF_BL 49152
#define GEMM_SMEM (3 * STAGE_BYTES)

__global__ __launch_bounds__(256, 1)
void gemm_q(const int8_t* __restrict__ Ah, const int8_t* __restrict__ Al,
            const float* __restrict__ aS, int ldA,
            const int8_t* __restrict__ Bh, const int8_t* __restrict__ Bl,
            const unsigned* __restrict__ bS, int ldB,
            const float* __restrict__ bias, int Kfull,
            float* __restrict__ C, int ldC,
            const int* __restrict__ gather, const int* __restrict__ scatter,
            unsigned* __restrict__ rmax,
            const int* __restrict__ cnt, int Mfix, int relu) {
    extern __shared__ char sm[];
    int count = cnt ? *cnt : Mfix;
    int m0 = blockIdx.y * 128;
    if (m0 >= count) return;
    int n0 = blockIdx.x * 128;
    uint32_t smb = smem_u32(sm);
    int tid = threadIdx.x, wid = tid >> 5, lane = tid & 31;

    // gmem->smem: row = tid>>1 (0..127), half = tid&1 (two 64B halves of 128B row)
    int row = tid >> 1, half = tid & 1;
    uint32_t swoff[4];
#pragma unroll
    for (int i = 0; i < 4; i++) {
        uint32_t bo = (uint32_t)row * 128 + half * 64 + i * 16;
        swoff[i] = bo ^ ((bo >> 3) & 0x70);
    }
    int ar = m0 + row; if (ar > count - 1) ar = count - 1;
    int ag = gather ? gather[ar] : ar;
    const int8_t* pah = Ah + (size_t)ag * ldA + half * 64;
    const int8_t* pal = Al + (size_t)ag * ldA + half * 64;
    const int8_t* pbh = Bh + (size_t)(n0 + row) * ldB + half * 64;
    const int8_t* pbl = Bl + (size_t)(n0 + row) * ldB + half * 64;

    int nch = Kfull >> 7;   // 128 K-elements per chunk

    int wr = wid >> 2, wc = wid & 3;
    int m_base = wr * 64, n_base = wc * 32;

    int acc_hh[4][4][4], acc_md[4][4][4];
#pragma unroll
    for (int a = 0; a < 4; a++)
#pragma unroll
        for (int b = 0; b < 4; b++)
#pragma unroll
            for (int c = 0; c < 4; c++) { acc_hh[a][b][c] = 0; acc_md[a][b][c] = 0; }

    // prologue: chunks 0,1
#pragma unroll
    for (int p = 0; p < 2; p++) {
        uint32_t st = smb + p * STAGE_BYTES;
        int ke = p * 128;
#pragma unroll
        for (int i = 0; i < 4; i++) {
            cp16(st + OFF_AH + swoff[i], pah + ke + i * 16);
            cp16(st + OFF_AL + swoff[i], pal + ke + i * 16);
            cp16(st + OFF_BH + swoff[i], pbh + ke + i * 16);
            cp16(st + OFF_BL + swoff[i], pbl + ke + i * 16);
        }
        CP_COMMIT();
    }

    int stage = 0;
    for (int c = 0; c < nch; c++) {
        if (c + 2 < nch) {
            int ws = (c + 2) % 3;
            uint32_t st = smb + ws * STAGE_BYTES;
            int ke = (c + 2) * 128;
#pragma unroll
            for (int i = 0; i < 4; i++) {
                cp16(st + OFF_AH + swoff[i], pah + ke + i * 16);
                cp16(st + OFF_AL + swoff[i], pal + ke + i * 16);
                cp16(st + OFF_BH + swoff[i], pbh + ke + i * 16);
                cp16(st + OFF_BL + swoff[i], pbl + ke + i * 16);
            }
            CP_COMMIT();
            CP_WAIT2();
        } else if (c + 1 < nch) {
            CP_WAIT1();
        } else {
            CP_WAIT0();
        }
        __syncthreads();

        uint32_t sb = smb + stage * STAGE_BYTES;
#pragma unroll
        for (int kk = 0; kk < 4; kk++) {   // kk = 32-byte (k32) step within 128B row
            uint32_t brw = n_base + ((lane & 7) | ((lane >> 1) & 8));
            uint32_t bkb = kk * 32 + ((lane >> 3) & 1) * 16;
            uint32_t bh[8], bl[8];
#pragma unroll
            for (int np = 0; np < 2; np++) {
                uint32_t bo = (brw + np * 16) * 128 + bkb;
                uint32_t ad = sb + (bo ^ ((bo >> 3) & 0x70));
                ldmx4(bh + np * 4, ad + OFF_BH);
                ldmx4(bl + np * 4, ad + OFF_BL);
            }
            uint32_t arw = m_base + (lane & 15);
            uint32_t akb = kk * 32 + ((lane >> 4) & 1) * 16;
#pragma unroll
            for (int mt = 0; mt < 4; mt++) {
                uint32_t bo = (arw + mt * 16) * 128 + akb;
                uint32_t ad = sb + (bo ^ ((bo >> 3) & 0x70));
                uint32_t ah[4], al[4];
                ldmx4(ah, ad + OFF_AH);
                ldmx4(al, ad + OFF_AL);
#pragma unroll
                for (int nt = 0; nt < 4; nt++) {
                    mma_s8(acc_hh[mt][nt], ah, bh[nt * 2], bh[nt * 2 + 1]);
                    mma_s8(acc_md[mt][nt], ah, bl[nt * 2], bl[nt * 2 + 1]);
                    mma_s8(acc_md[mt][nt], al, bh[nt * 2], bh[nt * 2 + 1]);
                }
            }
        }
        __syncthreads();
        stage = (stage + 1 == 3) ? 0 : stage + 1;
    }

    // epilogue: dequant + bias (+relu), stores, optional row-max
    const float INV2 = 1.0f / (QMAX * QMAX);
#pragma unroll
    for (int mt = 0; mt < 4; mt++) {
#pragma unroll
        for (int h2 = 0; h2 < 2; h2++) {
            int r = m0 + m_base + mt * 16 + h2 * 8 + (lane >> 2);
            if (r >= count) continue;
            int srow = gather ? gather[r] : r;
            float as = aS[srow] * INV2;
            int orow = scatter ? scatter[r] : r;
            float vmax = 0.f;
#pragma unroll
            for (int nt = 0; nt < 4; nt++) {
                int col = n0 + n_base + nt * 8 + (lane & 3) * 2;
                float bs0 = __uint_as_float(bS[col]);
                float bs1 = __uint_as_float(bS[col + 1]);
                float f0 = 16384.f * (float)acc_hh[mt][nt][h2 * 2 + 0] + 128.f * (float)acc_md[mt][nt][h2 * 2 + 0];
                float f1 = 16384.f * (float)acc_hh[mt][nt][h2 * 2 + 1] + 128.f * (float)acc_md[mt][nt][h2 * 2 + 1];
                float v0 = f0 * as * bs0 + bias[col];
                float v1 = f1 * as * bs1 + bias[col + 1];
                if (relu) { v0 = fmaxf(v0, 0.f); v1 = fmaxf(v1, 0.f); }
                float2 o; o.x = v0; o.y = v1;
                *(float2*)(C + (size_t)orow * ldC + col) = o;
                vmax = fmaxf(vmax, fmaxf(fabsf(v0), fabsf(v1)));
            }
            if (rmax) {
                vmax = fmaxf(vmax, __shfl_xor_sync(0xffffffffu, vmax, 1));
                vmax = fmaxf(vmax, __shfl_xor_sync(0xffffffffu, vmax, 2));
                if ((lane & 3) == 0) atomicMax(&rmax[r], __float_as_uint(vmax));
            }
        }
    }
}

// ---------------- quantize intermediate (f32 -> int8 limbs + row scale) ----------------
__global__ void quant_mid_kernel(const float* __restrict__ mid, int N,
                                 const unsigned* __restrict__ rmaxslot,
                                 float* __restrict__ sOut,
                                 int8_t* __restrict__ qh, int8_t* __restrict__ ql,
                                 const int* __restrict__ cnt) {
    int count = *cnt;
    size_t e = ((size_t)blockIdx.x * 256 + threadIdx.x) * 4;
    int r = (int)(e / N);
    if (r >= count) return;
    float s = __uint_as_float(rmaxslot[r]);
    if ((e & (size_t)(N - 1)) < 4) sOut[r] = s;
    float inv = s > 0.f ? QMAX / s : 0.f;
    float4 v = *(const float4*)(mid + e);
    char4 h, l;
    qsplit(v.x, inv, (int8_t&)h.x, (int8_t&)l.x);
    qsplit(v.y, inv, (int8_t&)h.y, (int8_t&)l.y);
    qsplit(v.z, inv, (int8_t&)h.z, (int8_t&)l.z);
    qsplit(v.w, inv, (int8_t&)h.w, (int8_t&)l.w);
    *(char4*)(qh + e) = h;
    *(char4*)(ql + e) = l;
}

// ---------------- logits + argmax + inline compaction (unambiguous) ----------------
__global__ void logits_kernel(const float* __restrict__ W2, const float* __restrict__ b2) {
    int warp = (blockIdx.x * blockDim.x + threadIdx.x) >> 5;
    int lane = threadIdx.x & 31;
    if (warp >= T_TOK) return;
    const float* hrow = g_hmid + (size_t)warp * 512;
    float s0 = 0.f, s1 = 0.f, s2 = 0.f;
    for (int k = lane * 4; k < 512; k += 128) {
        float4 h = *(const float4*)(hrow + k);
        const float* w = W2 + k * 3;
        s0 += h.x * w[0] + h.y * w[3] + h.z * w[6] + h.w * w[9];
        s1 += h.x * w[1] + h.y * w[4] + h.z * w[7] + h.w * w[10];
        s2 += h.x * w[2] + h.y * w[5] + h.z * w[8] + h.w * w[11];
    }
#pragma unroll
    for (int o = 16; o > 0; o >>= 1) {
        s0 += __shfl_xor_sync(0xffffffffu, s0, o);
        s1 += __shfl_xor_sync(0xffffffffu, s1, o);
        s2 += __shfl_xor_sync(0xffffffffu, s2, o);
    }
    if (lane == 0) {
        s0 += b2[0]; s1 += b2[1]; s2 += b2[2];
        int sel = 0; float best = s0;
        if (s1 > best) { best = s1; sel = 1; }
        if (s2 > best) { best = s2; sel = 2; }
        float second = (sel == 0) ? fmaxf(s1, s2) : (sel == 1 ? fmaxf(s0, s2) : fmaxf(s0, s1));
        g_sel[warp] = sel;
        if (best - second < 1e-3f) {
            int p = atomicAdd(&g_cnt[2], 1);
            g_fix[p] = warp;
        } else {
            if (sel == 1)      { int p = atomicAdd(&g_cnt[0], 1); g_idx1[p] = warp; }
            else if (sel == 2) { int p = atomicAdd(&g_cnt[1], 1); g_idx2[p] = warp; }
        }
    }
}

// ---------------- fp32 exact recompute + compaction for ambiguous tokens ----------------
__global__ void fixup_kernel(const float* __restrict__ W1, const float* __restrict__ b1,
                             const float* __restrict__ W2, const float* __restrict__ b2) {
    __shared__ float hm[512];
    __shared__ float red[256];
    __shared__ float logit[3];
    int nfix = g_cnt[2];
    for (int i = blockIdx.x; i < nfix; i += gridDim.x) {
        int t = g_fix[i];
        const float* cr = g_combined + (size_t)t * HDIM;
        int j0 = threadIdx.x, j1 = threadIdx.x + 256;
        float a0 = b1[j0], a1 = b1[j1];
#pragma unroll 4
        for (int k = 0; k < HDIM; k++) {
            float c = __ldg(cr + k);
            a0 += c * W1[(size_t)k * 512 + j0];
            a1 += c * W1[(size_t)k * 512 + j1];
        }
        hm[j0] = fmaxf(a0, 0.f);
        hm[j1] = fmaxf(a1, 0.f);
        __syncthreads();
        for (int l = 0; l < 3; l++) {
            float p = hm[threadIdx.x] * W2[threadIdx.x * 3 + l] +
                      hm[threadIdx.x + 256] * W2[(threadIdx.x + 256) * 3 + l];
            red[threadIdx.x] = p; __syncthreads();
            for (int o = 128; o > 0; o >>= 1) {
                if (threadIdx.x < o) red[threadIdx.x] += red[threadIdx.x + o];
                __syncthreads();
            }
            if (threadIdx.x == 0) logit[l] = red[0] + b2[l];
            __syncthreads();
        }
        if (threadIdx.x == 0) {
            float s0 = logit[0], s1 = logit[1], s2 = logit[2];
            int sel = 0; float best = s0;
            if (s1 > best) { best = s1; sel = 1; }
            if (s2 > best) { sel = 2; }
            g_sel[t] = sel;
            if (sel == 1)      { int p = atomicAdd(&g_cnt[0], 1); g_idx1[p] = t; }
            else if (sel == 2) { int p = atomicAdd(&g_cnt[1], 1); g_idx2[p] = t; }
        }
        __syncthreads();
    }
}

__global__ void copy0_kernel(const float* __restrict__ x, float* __restrict__ out) {
    int t = blockIdx.x;
    if (g_sel[t] != 0) return;
    const float4* src = (const float4*)(x + (size_t)t * HDIM);
    float4* dst = (float4*)(out + (size_t)t * HDIM);
    for (int i = threadIdx.x; i < HDIM / 4; i += blockDim.x) dst[i] = src[i];
}

// ---------------- launch ----------------
extern "C" void kernel_launch(void* const* d_in, const int* in_sizes, int n_in,
                              void* d_out, int out_size) {
    const float* x      = (const float*)d_in[0];
    const float* freq   = (const float*)d_in[1];
    const float* imp    = (const float*)d_in[2];
    const float* sel_W1 = (const float*)d_in[3];
    const float* sel_b1 = (const float*)d_in[4];
    const float* sel_W2 = (const float*)d_in[5];
    const float* sel_b2 = (const float*)d_in[6];
    const float* c1_W   = (const float*)d_in[7];
    const float* c1_b   = (const float*)d_in[8];
    const float* f1_W   = (const float*)d_in[9];
    const float* f1_b   = (const float*)d_in[10];
    const float* d1_W   = (const float*)d_in[11];
    const float* d1_b   = (const float*)d_in[12];
    const float* c2_W   = (const float*)d_in[13];
    const float* c2_b   = (const float*)d_in[14];
    const float* f2_W   = (const float*)d_in[15];
    const float* f2_b   = (const float*)d_in[16];
    const float* d2_W   = (const float*)d_in[17];
    const float* d2_b   = (const float*)d_in[18];
    float* out = (float*)d_out;

    int8_t *xqh, *xql, *cqh, *cql, *q1h, *q1l, *q2h, *q2l, *wqh, *wql;
    float *sx, *sc, *s1, *s2, *hmid, *mid;
    unsigned *rmax, *wmax;
    int *idx1, *idx2, *cnt;
    cudaGetSymbolAddress((void**)&xqh, g_xqh);
    cudaGetSymbolAddress((void**)&xql, g_xql);
    cudaGetSymbolAddress((void**)&cqh, g_cqh);
    cudaGetSymbolAddress((void**)&cql, g_cql);
    cudaGetSymbolAddress((void**)&q1h, g_q1h);
    cudaGetSymbolAddress((void**)&q1l, g_q1l);
    cudaGetSymbolAddress((void**)&q2h, g_q2h);
    cudaGetSymbolAddress((void**)&q2l, g_q2l);
    cudaGetSymbolAddress((void**)&wqh, g_wqh);
    cudaGetSymbolAddress((void**)&wql, g_wql);
    cudaGetSymbolAddress((void**)&sx, g_sx);
    cudaGetSymbolAddress((void**)&sc, g_sc);
    cudaGetSymbolAddress((void**)&s1, g_s1);
    cudaGetSymbolAddress((void**)&s2, g_s2);
    cudaGetSymbolAddress((void**)&hmid, g_hmid);
    cudaGetSymbolAddress((void**)&mid, g_mid);
    cudaGetSymbolAddress((void**)&rmax, g_rmax);
    cudaGetSymbolAddress((void**)&wmax, g_wmax);
    cudaGetSymbolAddress((void**)&idx1, g_idx1);
    cudaGetSymbolAddress((void**)&idx2, g_idx2);
    cudaGetSymbolAddress((void**)&cnt, g_cnt);

    cudaFuncSetAttribute(gemm_q, cudaFuncAttributeMaxDynamicSharedMemorySize, GEMM_SMEM);

    // 0: prep
    prep_kernel<<<T_TOK, 256>>>(x, freq, imp);

    // matrix tables (order: selW1, c1, f1, d1, c2, f2, d2)
    WAll slab, tile;
    int ss = 0, ts = 0;
    auto setw = [&](int i, const float* src, int K, int N, unsigned off) {
        slab.d[i].src = src; slab.d[i].K = K; slab.d[i].N = N; slab.d[i].off = off; slab.d[i].start = ss;
        ss += K / 32;
        tile.d[i].src = src; tile.d[i].K = K; tile.d[i].N = N; tile.d[i].off = off; tile.d[i].start = ts;
        ts += (N / 32) * (K / 32);
    };
    setw(0, sel_W1, 2048, 512,  O_SELW1);
    setw(1, c1_W,   2048, 1024, O_C1);
    setw(2, f1_W,   1024, 1024, O_F1);
    setw(3, d1_W,   1024, 2048, O_D1);
    setw(4, c2_W,   2048, 512,  O_C2);
    setw(5, f2_W,   512,  512,  O_F2);
    setw(6, d2_W,   512,  2048, O_D2);

    // 1-2: weight colmax + transpose/quantize
    wcolmax_kernel<<<ss, 256>>>(slab);
    transpose_quant_kernel<<<ts, dim3(32, 8)>>>(tile);

    const int MT = T_TOK / 128;

    // 3: selector hidden (relu, f32 out)
    gemm_q<<<dim3(512 / 128, MT), 256, GEMM_SMEM>>>(
        cqh, cql, sc, 2048, wqh + O_SELW1, wql + O_SELW1, wmax + 0 * 2048, 2048,
        sel_b1, 2048, hmid, 512, nullptr, nullptr, nullptr, nullptr, T_TOK, 1);

    // 4-5: selection
    logits_kernel<<<T_TOK / 8, 256>>>(sel_W2, sel_b2);
    fixup_kernel<<<64, 256>>>(sel_W1, sel_b1, sel_W2, sel_b2);

    // expert 1
    gemm_q<<<dim3(1024 / 128, MT), 256, GEMM_SMEM>>>(
        xqh, xql, sx, 2048, wqh + O_C1, wql + O_C1, wmax + 1 * 2048, 2048,
        c1_b, 2048, mid, 1024, idx1, nullptr, rmax + 0 * T_TOK, cnt + 0, 0, 0);
    quant_mid_kernel<<<T_TOK * 1024 / 1024, 256>>>(mid, 1024, rmax + 0 * T_TOK, s1, q1h, q1l, cnt + 0);
    gemm_q<<<dim3(1024 / 128, MT), 256, GEMM_SMEM>>>(
        q1h, q1l, s1, 1024, wqh + O_F1, wql + O_F1, wmax + 2 * 2048, 1024,
        f1_b, 1024, mid, 1024, nullptr, nullptr, rmax + 1 * T_TOK, cnt + 0, 0, 0);
    quant_mid_kernel<<<T_TOK * 1024 / 1024, 256>>>(mid, 1024, rmax + 1 * T_TOK, s2, q2h, q2l, cnt + 0);
    gemm_q<<<dim3(2048 / 128, MT), 256, GEMM_SMEM>>>(
        q2h, q2l, s2, 1024, wqh + O_D1, wql + O_D1, wmax + 3 * 2048, 1024,
        d1_b, 1024, out, 2048, nullptr, idx1, nullptr, cnt + 0, 0, 0);

    // identity tokens
    copy0_kernel<<<T_TOK, 128>>>(x, out);

    // expert 2
    gemm_q<<<dim3(512 / 128, MT), 256, GEMM_SMEM>>>(
        xqh, xql, sx, 2048, wqh + O_C2, wql + O_C2, wmax + 4 * 2048, 2048,
        c2_b, 2048, mid, 512, idx2, nullptr, rmax + 2 * T_TOK, cnt + 1, 0, 0);
    quant_mid_kernel<<<T_TOK * 512 / 1024, 256>>>(mid, 512, rmax + 2 * T_TOK, s1, q1h, q1l, cnt + 1);
    gemm_q<<<dim3(512 / 128, MT), 256, GEMM_SMEM>>>(
        q1h, q1l, s1, 512, wqh + O_F2, wql + O_F2, wmax + 5 * 2048, 512,
        f2_b, 512, mid, 512, nullptr, nullptr, rmax + 3 * T_TOK, cnt + 1, 0, 0);
    quant_mid_kernel<<<T_TOK * 512 / 1024, 256>>>(mid, 512, rmax + 3 * T_TOK, s2, q2h, q2l, cnt + 1);
    gemm_q<<<dim3(2048 / 128, MT), 256, GEMM_SMEM>>>(
        q2h, q2l, s2, 512, wqh + O_D2, wql + O_D2, wmax + 6 * 2048, 512,
        d2_b, 512, out, 2048, nullptr, idx2, nullptr, cnt + 1, 0, 0);
}

// round 15
// speedup vs baseline: 2.7498x; 2.7498x over previous
#include <cuda_runtime.h>
#include <cuda_fp16.h>
#include <cstdint>

#define T_TOK 16384
#define HDIM  2048

// ---------------- static device scratch ----------------
__device__ __align__(256) __half g_xh[(size_t)T_TOK * HDIM];   // x as fp16
__device__ __align__(256) __half g_ch[(size_t)T_TOK * HDIM];   // combined as fp16
__device__ float g_combined[(size_t)T_TOK * HDIM];             // combined f32 (fixup)
__device__ float g_hmid[(size_t)T_TOK * 512];
__device__ __align__(256) __half g_mA[(size_t)T_TOK * 1024];   // chained intermediates
__device__ __align__(256) __half g_mB[(size_t)T_TOK * 1024];
// transposed fp16 weights pool [N][K] layout (element offsets)
#define O_SELW1 0u
#define O_C1 1048576u
#define O_F1 3145728u
#define O_D1 4194304u
#define O_C2 6291456u
#define O_F2 7340032u
#define O_D2 7602176u
#define W_POOL 8650752u
__device__ __align__(256) __half g_w[W_POOL];
__device__ int g_sel[T_TOK];
__device__ int g_idx1[T_TOK];
__device__ int g_idx2[T_TOK];
__device__ int g_fix[T_TOK];
__device__ int g_cnt[4];   // [0]=cnt1 [1]=cnt2 [2]=nfix

// ---------------- helpers ----------------
__device__ __forceinline__ uint32_t smem_u32(const void* p) {
    uint32_t a;
    asm("{ .reg .u64 t; cvta.to.shared.u64 t, %1; cvt.u32.u64 %0, t; }" : "=r"(a) : "l"(p));
    return a;
}
__device__ __forceinline__ void cp16(uint32_t dst, const void* src) {
    asm volatile("cp.async.cg.shared.global [%0], [%1], 16;" :: "r"(dst), "l"(src));
}
#define CP_COMMIT() asm volatile("cp.async.commit_group;" ::: "memory")
#define CP_WAIT2()  asm volatile("cp.async.wait_group 2;" ::: "memory")
#define CP_WAIT1()  asm volatile("cp.async.wait_group 1;" ::: "memory")
#define CP_WAIT0()  asm volatile("cp.async.wait_group 0;" ::: "memory")

__device__ __forceinline__ void ldmx4(uint32_t* r, uint32_t addr) {
    asm volatile("ldmatrix.sync.aligned.m8n8.x4.shared.b16 {%0,%1,%2,%3}, [%4];"
        : "=r"(r[0]), "=r"(r[1]), "=r"(r[2]), "=r"(r[3]) : "r"(addr));
}
__device__ __forceinline__ void mma_f16(float* c, const uint32_t* a, uint32_t b0, uint32_t b1) {
    asm volatile("mma.sync.aligned.m16n8k16.row.col.f32.f16.f16.f32 "
        "{%0,%1,%2,%3}, {%4,%5,%6,%7}, {%8,%9}, {%0,%1,%2,%3};"
        : "+f"(c[0]), "+f"(c[1]), "+f"(c[2]), "+f"(c[3])
        : "r"(a[0]), "r"(a[1]), "r"(a[2]), "r"(a[3]), "r"(b0), "r"(b1));
}

// ---------------- prep: combined + fp16 conversions, init counters ----------------
__global__ void prep_kernel(const float* __restrict__ x, const float* __restrict__ freq,
                            const float* __restrict__ imp) {
    if (blockIdx.x == 0 && threadIdx.x < 4) g_cnt[threadIdx.x] = 0;
    size_t e = ((size_t)blockIdx.x * 256 + threadIdx.x) * 4;
    if (e >= (size_t)T_TOK * HDIM) return;
    int t = (int)(e / HDIM);
    int h = (int)(e % HDIM);
    float s = (h < 1024) ? freq[t] : imp[t];
    float4 v = *(const float4*)(x + e);
    float4 c; c.x = v.x * s; c.y = v.y * s; c.z = v.z * s; c.w = v.w * s;
    *(float4*)(g_combined + e) = c;
    __half xh[4] = {__float2half_rn(v.x), __float2half_rn(v.y),
                    __float2half_rn(v.z), __float2half_rn(v.w)};
    __half chh[4] = {__float2half_rn(c.x), __float2half_rn(c.y),
                     __float2half_rn(c.z), __float2half_rn(c.w)};
    *(uint2*)(g_xh + e) = *(uint2*)xh;
    *(uint2*)(g_ch + e) = *(uint2*)chh;
}

// ---------------- merged weight transpose to fp16 [N][K] ----------------
struct WDesc { const float* src; int K; int N; unsigned off; int start; };
struct WAll  { WDesc d[7]; };

__global__ void transpose_all_kernel(WAll wa) {
    __shared__ float tile[32][33];
    int bt = blockIdx.x;
    int mi = 0;
#pragma unroll
    for (int i = 1; i < 7; i++) if (bt >= wa.d[i].start) mi = i;
    const WDesc& d = wa.d[mi];
    int lt = bt - d.start;
    int ntiles_n = d.N / 32;
    int nb = (lt % ntiles_n) * 32;
    int kb = (lt / ntiles_n) * 32;
#pragma unroll
    for (int r = 0; r < 4; r++) {
        int k = kb + threadIdx.y + r * 8;
        tile[threadIdx.y + r * 8][threadIdx.x] = d.src[(size_t)k * d.N + nb + threadIdx.x];
    }
    __syncthreads();
#pragma unroll
    for (int r = 0; r < 4; r++) {
        int n = nb + threadIdx.y + r * 8;
        int k = kb + threadIdx.x;
        g_w[d.off + (size_t)n * d.K + k] = __float2half_rn(tile[threadIdx.x][threadIdx.y + r * 8]);
    }
}

// ---------------- fp16 mma.sync GEMM ----------------
// CTA tile 128x128, 8 warps each 64x32. BK=64 fp16 (128B rows, SW128 swizzle).
// 3-stage cp.async ring, single-term fp16 MMA (fp32 accum).
#define STAGE_BYTES 32768
#define OFF_A 0
#define OFF_B 16384
#define GEMM_SMEM (3 * STAGE_BYTES)

__global__ __launch_bounds__(256, 1)
void gemm_h(const __half* __restrict__ A, int ldA,
            const __half* __restrict__ B, int ldB,
            const float* __restrict__ bias, int Kfull,
            float* __restrict__ Cf, int ldCf,
            __half* __restrict__ Ch, int ldCb,
            const int* __restrict__ gather, const int* __restrict__ scatter,
            const int* __restrict__ cnt, int Mfix, int relu) {
    extern __shared__ char sm[];
    int count = cnt ? *cnt : Mfix;
    int m0 = blockIdx.y * 128;
    if (m0 >= count) return;
    int n0 = blockIdx.x * 128;
    uint32_t smb = smem_u32(sm);
    int tid = threadIdx.x, wid = tid >> 5, lane = tid & 31;

    // gmem->smem: row = tid>>1 (0..127), half-row = tid&1 (two 64B halves of 128B row)
    int row = tid >> 1, hf = tid & 1;
    uint32_t swoff[4];
#pragma unroll
    for (int i = 0; i < 4; i++) {
        uint32_t bo = (uint32_t)row * 128 + hf * 64 + i * 16;
        swoff[i] = bo ^ ((bo >> 3) & 0x70);
    }
    int ar = m0 + row; if (ar > count - 1) ar = count - 1;
    int ag = gather ? gather[ar] : ar;
    const __half* pa = A + (size_t)ag * ldA + hf * 32;
    const __half* pb = B + (size_t)(n0 + row) * ldB + hf * 32;

    int nch = Kfull >> 6;

    int wr = wid >> 2, wc = wid & 3;
    int m_base = wr * 64, n_base = wc * 32;

    float acc[4][4][4];
#pragma unroll
    for (int a = 0; a < 4; a++)
#pragma unroll
        for (int b = 0; b < 4; b++)
#pragma unroll
            for (int c = 0; c < 4; c++) acc[a][b][c] = 0.f;

    // prologue: chunks 0,1 -> stages 0,1
#pragma unroll
    for (int p = 0; p < 2; p++) {
        uint32_t st = smb + p * STAGE_BYTES;
        int ke = p * 64;
#pragma unroll
        for (int i = 0; i < 4; i++) {
            cp16(st + OFF_A + swoff[i], pa + ke + i * 8);
            cp16(st + OFF_B + swoff[i], pb + ke + i * 8);
        }
        CP_COMMIT();
    }

    int stage = 0;
    for (int c = 0; c < nch; c++) {
        if (c + 2 < nch) {
            int ws = (c + 2) % 3;
            uint32_t st = smb + ws * STAGE_BYTES;
            int ke = (c + 2) * 64;
#pragma unroll
            for (int i = 0; i < 4; i++) {
                cp16(st + OFF_A + swoff[i], pa + ke + i * 8);
                cp16(st + OFF_B + swoff[i], pb + ke + i * 8);
            }
            CP_COMMIT();
            CP_WAIT2();
        } else if (c + 1 < nch) {
            CP_WAIT1();
        } else {
            CP_WAIT0();
        }
        __syncthreads();

        uint32_t sb = smb + stage * STAGE_BYTES;
#pragma unroll
        for (int kk = 0; kk < 4; kk++) {
            uint32_t brw = n_base + ((lane & 7) | ((lane >> 1) & 8));
            uint32_t bkb = kk * 32 + ((lane >> 3) & 1) * 16;
            uint32_t bh[8];
#pragma unroll
            for (int np = 0; np < 2; np++) {
                uint32_t bo = (brw + np * 16) * 128 + bkb;
                uint32_t ad = sb + (bo ^ ((bo >> 3) & 0x70));
                ldmx4(bh + np * 4, ad + OFF_B);
            }
            uint32_t arw = m_base + (lane & 15);
            uint32_t akb = kk * 32 + ((lane >> 4) & 1) * 16;
#pragma unroll
            for (int mt = 0; mt < 4; mt++) {
                uint32_t bo = (arw + mt * 16) * 128 + akb;
                uint32_t ad = sb + (bo ^ ((bo >> 3) & 0x70));
                uint32_t ah[4];
                ldmx4(ah, ad + OFF_A);
#pragma unroll
                for (int nt = 0; nt < 4; nt++)
                    mma_f16(acc[mt][nt], ah, bh[nt * 2], bh[nt * 2 + 1]);
            }
        }
        __syncthreads();
        stage = (stage + 1 == 3) ? 0 : stage + 1;
    }

    // epilogue: bias (+relu), direct stores (f32 and/or fp16)
#pragma unroll
    for (int mt = 0; mt < 4; mt++) {
#pragma unroll
        for (int h2 = 0; h2 < 2; h2++) {
            int r = m0 + m_base + mt * 16 + h2 * 8 + (lane >> 2);
            if (r >= count) continue;
            int orow = scatter ? scatter[r] : r;
#pragma unroll
            for (int nt = 0; nt < 4; nt++) {
                int col = n0 + n_base + nt * 8 + (lane & 3) * 2;
                float v0 = acc[mt][nt][h2 * 2 + 0] + bias[col];
                float v1 = acc[mt][nt][h2 * 2 + 1] + bias[col + 1];
                if (relu) { v0 = fmaxf(v0, 0.f); v1 = fmaxf(v1, 0.f); }
                if (Cf) {
                    float2 o; o.x = v0; o.y = v1;
                    *(float2*)(Cf + (size_t)orow * ldCf + col) = o;
                }
                if (Ch) {
                    __half hv[2] = {__float2half_rn(v0), __float2half_rn(v1)};
                    *(uint32_t*)(Ch + (size_t)r * ldCb + col) = *(uint32_t*)hv;
                }
            }
        }
    }
}

// ---------------- logits + argmax + inline compaction (unambiguous) ----------------
__global__ void logits_kernel(const float* __restrict__ W2, const float* __restrict__ b2) {
    int warp = (blockIdx.x * blockDim.x + threadIdx.x) >> 5;
    int lane = threadIdx.x & 31;
    if (warp >= T_TOK) return;
    const float* hrow = g_hmid + (size_t)warp * 512;
    float s0 = 0.f, s1 = 0.f, s2 = 0.f;
    for (int k = lane * 4; k < 512; k += 128) {
        float4 h = *(const float4*)(hrow + k);
        const float* w = W2 + k * 3;
        s0 += h.x * w[0] + h.y * w[3] + h.z * w[6] + h.w * w[9];
        s1 += h.x * w[1] + h.y * w[4] + h.z * w[7] + h.w * w[10];
        s2 += h.x * w[2] + h.y * w[5] + h.z * w[8] + h.w * w[11];
    }
#pragma unroll
    for (int o = 16; o > 0; o >>= 1) {
        s0 += __shfl_xor_sync(0xffffffffu, s0, o);
        s1 += __shfl_xor_sync(0xffffffffu, s1, o);
        s2 += __shfl_xor_sync(0xffffffffu, s2, o);
    }
    if (lane == 0) {
        s0 += b2[0]; s1 += b2[1]; s2 += b2[2];
        int sel = 0; float best = s0;
        if (s1 > best) { best = s1; sel = 1; }
        if (s2 > best) { best = s2; sel = 2; }
        float second = (sel == 0) ? fmaxf(s1, s2) : (sel == 1 ? fmaxf(s0, s2) : fmaxf(s0, s1));
        g_sel[warp] = sel;
        if (best - second < 1e-3f) {
            int p = atomicAdd(&g_cnt[2], 1);
            g_fix[p] = warp;
        } else {
            if (sel == 1)      { int p = atomicAdd(&g_cnt[0], 1); g_idx1[p] = warp; }
            else if (sel == 2) { int p = atomicAdd(&g_cnt[1], 1); g_idx2[p] = warp; }
        }
    }
}

// ---------------- fp32 exact recompute + compaction for ambiguous tokens ----------------
__global__ void fixup_kernel(const float* __restrict__ W1, const float* __restrict__ b1,
                             const float* __restrict__ W2, const float* __restrict__ b2) {
    __shared__ float hm[512];
    __shared__ float red[256];
    __shared__ float logit[3];
    int nfix = g_cnt[2];
    for (int i = blockIdx.x; i < nfix; i += gridDim.x) {
        int t = g_fix[i];
        const float* cr = g_combined + (size_t)t * HDIM;
        int j0 = threadIdx.x, j1 = threadIdx.x + 256;
        float a0 = b1[j0], a1 = b1[j1];
#pragma unroll 4
        for (int k = 0; k < HDIM; k++) {
            float c = __ldg(cr + k);
            a0 += c * W1[(size_t)k * 512 + j0];
            a1 += c * W1[(size_t)k * 512 + j1];
        }
        hm[j0] = fmaxf(a0, 0.f);
        hm[j1] = fmaxf(a1, 0.f);
        __syncthreads();
        for (int l = 0; l < 3; l++) {
            float p = hm[threadIdx.x] * W2[threadIdx.x * 3 + l] +
                      hm[threadIdx.x + 256] * W2[(threadIdx.x + 256) * 3 + l];
            red[threadIdx.x] = p; __syncthreads();
            for (int o = 128; o > 0; o >>= 1) {
                if (threadIdx.x < o) red[threadIdx.x] += red[threadIdx.x + o];
                __syncthreads();
            }
            if (threadIdx.x == 0) logit[l] = red[0] + b2[l];
            __syncthreads();
        }
        if (threadIdx.x == 0) {
            float s0 = logit[0], s1 = logit[1], s2 = logit[2];
            int sel = 0; float best = s0;
            if (s1 > best) { best = s1; sel = 1; }
            if (s2 > best) { sel = 2; }
            g_sel[t] = sel;
            if (sel == 1)      { int p = atomicAdd(&g_cnt[0], 1); g_idx1[p] = t; }
            else if (sel == 2) { int p = atomicAdd(&g_cnt[1], 1); g_idx2[p] = t; }
        }
        __syncthreads();
    }
}

__global__ void copy0_kernel(const float* __restrict__ x, float* __restrict__ out) {
    int t = blockIdx.x;
    if (g_sel[t] != 0) return;
    const float4* src = (const float4*)(x + (size_t)t * HDIM);
    float4* dst = (float4*)(out + (size_t)t * HDIM);
    for (int i = threadIdx.x; i < HDIM / 4; i += blockDim.x) dst[i] = src[i];
}

// ---------------- launch ----------------
extern "C" void kernel_launch(void* const* d_in, const int* in_sizes, int n_in,
                              void* d_out, int out_size) {
    const float* x      = (const float*)d_in[0];
    const float* freq   = (const float*)d_in[1];
    const float* imp    = (const float*)d_in[2];
    const float* sel_W1 = (const float*)d_in[3];
    const float* sel_b1 = (const float*)d_in[4];
    const float* sel_W2 = (const float*)d_in[5];
    const float* sel_b2 = (const float*)d_in[6];
    const float* c1_W   = (const float*)d_in[7];
    const float* c1_b   = (const float*)d_in[8];
    const float* f1_W   = (const float*)d_in[9];
    const float* f1_b   = (const float*)d_in[10];
    const float* d1_W   = (const float*)d_in[11];
    const float* d1_b   = (const float*)d_in[12];
    const float* c2_W   = (const float*)d_in[13];
    const float* c2_b   = (const float*)d_in[14];
    const float* f2_W   = (const float*)d_in[15];
    const float* f2_b   = (const float*)d_in[16];
    const float* d2_W   = (const float*)d_in[17];
    const float* d2_b   = (const float*)d_in[18];
    float* out = (float*)d_out;

    __half *xh, *ch, *mA, *mB, *w;
    float *hmid;
    int *idx1, *idx2, *cnt;
    cudaGetSymbolAddress((void**)&xh, g_xh);
    cudaGetSymbolAddress((void**)&ch, g_ch);
    cudaGetSymbolAddress((void**)&mA, g_mA);
    cudaGetSymbolAddress((void**)&mB, g_mB);
    cudaGetSymbolAddress((void**)&w, g_w);
    cudaGetSymbolAddress((void**)&hmid, g_hmid);
    cudaGetSymbolAddress((void**)&idx1, g_idx1);
    cudaGetSymbolAddress((void**)&idx2, g_idx2);
    cudaGetSymbolAddress((void**)&cnt, g_cnt);

    cudaFuncSetAttribute(gemm_h, cudaFuncAttributeMaxDynamicSharedMemorySize, GEMM_SMEM);

    // 0: prep (combined + fp16 conversions + counter init)
    prep_kernel<<<T_TOK * HDIM / 1024, 256>>>(x, freq, imp);

    // 1: merged weight transpose
    WAll wa;
    int ts = 0;
    auto setw = [&](int i, const float* src, int K, int N, unsigned off) {
        wa.d[i].src = src; wa.d[i].K = K; wa.d[i].N = N; wa.d[i].off = off;
        wa.d[i].start = ts; ts += (N / 32) * (K / 32);
    };
    setw(0, sel_W1, 2048, 512,  O_SELW1);
    setw(1, c1_W,   2048, 1024, O_C1);
    setw(2, f1_W,   1024, 1024, O_F1);
    setw(3, d1_W,   1024, 2048, O_D1);
    setw(4, c2_W,   2048, 512,  O_C2);
    setw(5, f2_W,   512,  512,  O_F2);
    setw(6, d2_W,   512,  2048, O_D2);
    transpose_all_kernel<<<ts, dim3(32, 8)>>>(wa);

    const int MT = T_TOK / 128;

    // 2: selector hidden (relu, f32 out)
    gemm_h<<<dim3(512 / 128, MT), 256, GEMM_SMEM>>>(
        ch, 2048, w + O_SELW1, 2048, sel_b1, 2048,
        hmid, 512, nullptr, 0, nullptr, nullptr, nullptr, T_TOK, 1);

    // 3-4: selection
    logits_kernel<<<T_TOK / 8, 256>>>(sel_W2, sel_b2);
    fixup_kernel<<<64, 256>>>(sel_W1, sel_b1, sel_W2, sel_b2);

    // 5: expert-1 c1 GEMM (profiled by ncu -s 5 -c 1)
    gemm_h<<<dim3(1024 / 128, MT), 256, GEMM_SMEM>>>(
        xh, 2048, w + O_C1, 2048, c1_b, 2048,
        nullptr, 0, mA, 1024, idx1, nullptr, cnt + 0, 0, 0);

    // 6: identity tokens
    copy0_kernel<<<T_TOK, 128>>>(x, out);

    // expert 1 tail
    gemm_h<<<dim3(1024 / 128, MT), 256, GEMM_SMEM>>>(
        mA, 1024, w + O_F1, 1024, f1_b, 1024,
        nullptr, 0, mB, 1024, nullptr, nullptr, cnt + 0, 0, 0);
    gemm_h<<<dim3(2048 / 128, MT), 256, GEMM_SMEM>>>(
        mB, 1024, w + O_D1, 1024, d1_b, 1024,
        out, 2048, nullptr, 0, nullptr, idx1, cnt + 0, 0, 0);

    // expert 2
    gemm_h<<<dim3(512 / 128, MT), 256, GEMM_SMEM>>>(
        xh, 2048, w + O_C2, 2048, c2_b, 2048,
        nullptr, 0, mA, 512, idx2, nullptr, cnt + 1, 0, 0);
    gemm_h<<<dim3(512 / 128, MT), 256, GEMM_SMEM>>>(
        mA, 512, w + O_F2, 512, f2_b, 512,
        nullptr, 0, mB, 512, nullptr, nullptr, cnt + 1, 0, 0);
    gemm_h<<<dim3(2048 / 128, MT), 256, GEMM_SMEM>>>(
        mB, 512, w + O_D2, 512, d2_b, 512,
        out, 2048, nullptr, 0, nullptr, idx2, cnt + 1, 0, 0);
}